// round 2
// baseline (speedup 1.0000x reference)
#include <cuda_runtime.h>
#include <math.h>

#define BB 16
#define SS 2048
#define DD 768
#define BS (BB*SS)

// ---------------- device scratch (no allocations allowed) ----------------
__device__ float d_weff[DD*3 + 8];      // [d*3+k]; beff at [DD*3]
__device__ float d_g[BS*3];             // G[b*S+t][k] = sum_d weff[d,k]*x[b,t,d]
__device__ float d_alpha[BS];           // sigmoid logits -> alphas
__device__ int   d_tend[BS];            // fire timestep of output row r (per batch)
__device__ float d_wbeg[BS + 8];        // weight for x[t_begin] of row r (= a2 of previous fire)
__device__ float d_wend[BS];            // weight for x[t_end] of row r (= a1)
__device__ int   d_nf[BB];              // fires per batch

// ---------------- 1) collapse conv+linear: w_eff[d,k] ----------------
__global__ void k_weff(const float* __restrict__ conv_w, const float* __restrict__ conv_b,
                       const float* __restrict__ lin_w,  const float* __restrict__ lin_b) {
    int j = blockIdx.x * blockDim.x + threadIdx.x;   // j = d*3 + k, 0..2303
    if (j < DD*3) {
        float s = 0.f;
        #pragma unroll 4
        for (int o = 0; o < DD; ++o)
            s = fmaf(lin_w[o], conv_w[(size_t)o * (DD*3) + j], s);
        d_weff[j] = s;
    }
    if (j == 0) {
        float s = lin_b[0];
        for (int o = 0; o < DD; ++o)
            s = fmaf(lin_w[o], conv_b[o], s);
        d_weff[DD*3] = s;   // b_eff
    }
}

// ---------------- 2) G[b,t,k]: one warp per row ----------------
__global__ void k_g(const float* __restrict__ x) {
    __shared__ float sw[DD*3];
    for (int i = threadIdx.x; i < DD*3; i += blockDim.x) sw[i] = d_weff[i];
    __syncthreads();
    int warp = threadIdx.x >> 5, lane = threadIdx.x & 31;
    int row  = blockIdx.x * (blockDim.x >> 5) + warp;    // 0..BS-1
    if (row >= BS) return;
    const float* xr = x + (size_t)row * DD;
    float s0 = 0.f, s1 = 0.f, s2 = 0.f;
    #pragma unroll 6
    for (int d = lane; d < DD; d += 32) {
        float v = xr[d];
        s0 = fmaf(v, sw[d*3+0], s0);
        s1 = fmaf(v, sw[d*3+1], s1);
        s2 = fmaf(v, sw[d*3+2], s2);
    }
    #pragma unroll
    for (int o = 16; o; o >>= 1) {
        s0 += __shfl_xor_sync(0xFFFFFFFFu, s0, o);
        s1 += __shfl_xor_sync(0xFFFFFFFFu, s1, o);
        s2 += __shfl_xor_sync(0xFFFFFFFFu, s2, o);
    }
    if (lane == 0) {
        d_g[row*3+0] = s0; d_g[row*3+1] = s1; d_g[row*3+2] = s2;
    }
}

// ---------------- 3) alpha = sigmoid(G[s-1,0]+G[s,1]+G[s+1,2]+beff) ----------------
__global__ void k_alpha() {
    int idx = blockIdx.x * blockDim.x + threadIdx.x;     // b*S + s
    if (idx >= BS) return;
    int s = idx & (SS - 1);
    float pre = d_weff[DD*3];
    if (s > 0)      pre += d_g[(idx-1)*3 + 0];
    pre += d_g[idx*3 + 1];
    if (s < SS-1)   pre += d_g[(idx+1)*3 + 2];
    d_alpha[idx] = 1.f / (1.f + expf(-pre));
}

// ---------------- 4) scalar CIF scan per batch (replicates ref fp32 op order) ----------------
__global__ void k_scan(const int* __restrict__ lens, float* __restrict__ out_len, int write_len) {
    int b = blockIdx.x;
    if (threadIdx.x != 0) return;
    int len = lens[b];
    if (len > SS) len = SS;
    if (len < 0)  len = 0;
    const float* al = d_alpha + b*SS;
    int base = b*SS;
    float aacc = 0.f;
    int nf = 0;
    d_wbeg[base] = 0.f;
    for (int t = 0; t < len; ++t) {
        float a = al[t];
        float aacc_u = aacc + a;
        if (aacc_u >= 1.0f) {
            float a1 = 1.0f - aacc;
            float a2 = a - a1;
            d_tend[base + nf] = t;
            d_wend[base + nf] = a1;
            d_wbeg[base + nf + 1] = a2;
            nf++;
            aacc = a2;
        } else {
            aacc = aacc_u;
        }
    }
    d_nf[b] = nf;
    if (write_len) out_len[b] = (float)nf;
}

// ---------------- 5) emit: segmented weighted sum, one block per (row, batch) ----------------
__global__ void k_emit(const float* __restrict__ x, float* __restrict__ out) {
    int r = blockIdx.x, b = blockIdx.y;
    int tid = threadIdx.x;                                // 256 threads, 3 elems each
    float* orow = out + ((size_t)b*SS + r) * DD;
    int nf = d_nf[b];
    if (r >= nf) {
        orow[tid] = 0.f; orow[tid+256] = 0.f; orow[tid+512] = 0.f;
        return;
    }
    int base = b*SS;
    int t1 = d_tend[base + r];
    int t0 = (r == 0) ? -1 : d_tend[base + r - 1];
    const float* xb = x + (size_t)b*SS*DD;
    float a0 = 0.f, a1 = 0.f, a2 = 0.f;
    if (r > 0) {
        float w = d_wbeg[base + r];
        const float* xr = xb + (size_t)t0 * DD;
        a0 = w * xr[tid]; a1 = w * xr[tid+256]; a2 = w * xr[tid+512];
    }
    for (int t = t0 + 1; t < t1; ++t) {
        float w = d_alpha[base + t];
        const float* xr = xb + (size_t)t * DD;
        a0 = fmaf(w, xr[tid],     a0);
        a1 = fmaf(w, xr[tid+256], a1);
        a2 = fmaf(w, xr[tid+512], a2);
    }
    {
        float w = d_wend[base + r];
        const float* xr = xb + (size_t)t1 * DD;
        a0 = fmaf(w, xr[tid],     a0);
        a1 = fmaf(w, xr[tid+256], a1);
        a2 = fmaf(w, xr[tid+512], a2);
    }
    orow[tid] = a0; orow[tid+256] = a1; orow[tid+512] = a2;
}

extern "C" void kernel_launch(void* const* d_in, const int* in_sizes, int n_in,
                              void* d_out, int out_size) {
    const float* x      = (const float*)d_in[0];   // (B,S,D) f32
    const int*   lens   = (const int*)  d_in[1];   // (B,) i32
    const float* conv_w = (const float*)d_in[2];   // (D,D,3)
    const float* conv_b = (const float*)d_in[3];   // (D,)
    const float* lin_w  = (const float*)d_in[4];   // (1,D)
    const float* lin_b  = (const float*)d_in[5];   // (1,)
    float* out = (float*)d_out;

    const int BSD = BB * SS * DD;
    int write_len = (out_size >= BSD + BB) ? 1 : 0;

    k_weff <<<9, 256>>>(conv_w, conv_b, lin_w, lin_b);
    k_g    <<<BS / 8, 256>>>(x);
    k_alpha<<<BS / 256, 256>>>();
    k_scan <<<BB, 32>>>(lens, out + BSD, write_len);
    k_emit <<<dim3(SS, BB), 256>>>(x, out);
}

// round 3
// speedup vs baseline: 3.5433x; 3.5433x over previous
#include <cuda_runtime.h>
#include <math.h>

#define BB 16
#define SS 2048
#define DD 768
#define BS (BB*SS)
#define OCHUNKS 16
#define OPER (DD/OCHUNKS)   // 48

// ---------------- device scratch (no allocations allowed) ----------------
__device__ float d_part[OCHUNKS][DD*3];  // partial weff sums per o-chunk
__device__ float d_weff[DD*3 + 8];       // [d*3+k]; beff at [DD*3]
__device__ float d_g[BS*3];              // G[b*S+t][k]
__device__ float d_alpha[BS];
__device__ int   d_tend[BS];
__device__ float d_wbeg[BS + 8];
__device__ float d_wend[BS];
__device__ int   d_nf[BB];

// ---------------- 1a) partial weff: grid (9, 16), coalesced over j ----------------
__global__ void k_weff(const float* __restrict__ conv_w, const float* __restrict__ lin_w) {
    int j = blockIdx.x * 256 + threadIdx.x;          // 0..2303
    if (j >= DD*3) return;
    int o0 = blockIdx.y * OPER;
    float s = 0.f;
    #pragma unroll 8
    for (int oo = 0; oo < OPER; ++oo) {
        int o = o0 + oo;
        s = fmaf(__ldg(&lin_w[o]), conv_w[(size_t)o * (DD*3) + j], s);
    }
    d_part[blockIdx.y][j] = s;
}

// ---------------- 1b) reduce partials (deterministic) + beff ----------------
__global__ void k_weff2(const float* __restrict__ conv_b,
                        const float* __restrict__ lin_w, const float* __restrict__ lin_b) {
    if (blockIdx.x < 9) {
        int j = blockIdx.x * 256 + threadIdx.x;
        if (j < DD*3) {
            float s = 0.f;
            #pragma unroll
            for (int c = 0; c < OCHUNKS; ++c) s += d_part[c][j];
            d_weff[j] = s;
        }
    } else {
        // block 9: beff = lin_b + lin_w . conv_b, block reduction
        __shared__ float red[256];
        int t = threadIdx.x;
        float s = 0.f;
        for (int o = t; o < DD; o += 256) s = fmaf(lin_w[o], conv_b[o], s);
        red[t] = s;
        __syncthreads();
        for (int off = 128; off; off >>= 1) {
            if (t < off) red[t] += red[t + off];
            __syncthreads();
        }
        if (t == 0) d_weff[DD*3] = red[0] + lin_b[0];
    }
}

// ---------------- 2) G[b,t,k]: one warp per row, float4 ----------------
__global__ void k_g(const float* __restrict__ x) {
    __shared__ float s0[DD], s1[DD], s2[DD];
    for (int i = threadIdx.x; i < DD; i += blockDim.x) {
        s0[i] = d_weff[i*3+0];
        s1[i] = d_weff[i*3+1];
        s2[i] = d_weff[i*3+2];
    }
    __syncthreads();
    int warp = threadIdx.x >> 5, lane = threadIdx.x & 31;
    int row  = blockIdx.x * (blockDim.x >> 5) + warp;    // 0..BS-1
    if (row >= BS) return;
    const float4* xr = (const float4*)(x + (size_t)row * DD);
    const float4* w0 = (const float4*)s0;
    const float4* w1 = (const float4*)s1;
    const float4* w2 = (const float4*)s2;
    float a0 = 0.f, a1 = 0.f, a2 = 0.f;
    #pragma unroll
    for (int i = 0; i < DD/128; ++i) {                   // 6 iterations
        int d4 = lane + i*32;
        float4 v = xr[d4];
        float4 c0 = w0[d4], c1 = w1[d4], c2 = w2[d4];
        a0 = fmaf(v.x, c0.x, fmaf(v.y, c0.y, fmaf(v.z, c0.z, fmaf(v.w, c0.w, a0))));
        a1 = fmaf(v.x, c1.x, fmaf(v.y, c1.y, fmaf(v.z, c1.z, fmaf(v.w, c1.w, a1))));
        a2 = fmaf(v.x, c2.x, fmaf(v.y, c2.y, fmaf(v.z, c2.z, fmaf(v.w, c2.w, a2))));
    }
    #pragma unroll
    for (int o = 16; o; o >>= 1) {
        a0 += __shfl_xor_sync(0xFFFFFFFFu, a0, o);
        a1 += __shfl_xor_sync(0xFFFFFFFFu, a1, o);
        a2 += __shfl_xor_sync(0xFFFFFFFFu, a2, o);
    }
    if (lane == 0) {
        d_g[row*3+0] = a0; d_g[row*3+1] = a1; d_g[row*3+2] = a2;
    }
}

// ---------------- 3) alpha = sigmoid(G[s-1,0]+G[s,1]+G[s+1,2]+beff) ----------------
__global__ void k_alpha() {
    int idx = blockIdx.x * blockDim.x + threadIdx.x;
    if (idx >= BS) return;
    int s = idx & (SS - 1);
    float pre = d_weff[DD*3];
    if (s > 0)      pre += d_g[(idx-1)*3 + 0];
    pre += d_g[idx*3 + 1];
    if (s < SS-1)   pre += d_g[(idx+1)*3 + 2];
    d_alpha[idx] = 1.f / (1.f + expf(-pre));
}

// ---------------- 4) scalar CIF scan per batch, alphas staged in SMEM ----------------
__global__ void k_scan(const int* __restrict__ lens, float* __restrict__ out_len, int write_len) {
    __shared__ float sa[SS];
    int b = blockIdx.x;
    int len = lens[b];
    if (len > SS) len = SS;
    if (len < 0)  len = 0;
    const float* al = d_alpha + b*SS;
    for (int i = threadIdx.x; i < len; i += blockDim.x) sa[i] = al[i];
    __syncthreads();
    if (threadIdx.x != 0) return;
    int base = b*SS;
    float aacc = 0.f;
    int nf = 0;
    #pragma unroll 4
    for (int t = 0; t < len; ++t) {
        float a = sa[t];
        float aacc_u = aacc + a;
        float a1 = 1.0f - aacc;       // exact ref op order for fire bookkeeping
        float a2 = a - a1;
        bool fire = (aacc_u >= 1.0f);
        if (fire) {
            d_tend[base + nf] = t;
            d_wend[base + nf] = a1;
            d_wbeg[base + nf + 1] = a2;
            nf++;
        }
        aacc = fire ? a2 : aacc_u;
    }
    d_nf[b] = nf;
    if (write_len) out_len[b] = (float)nf;
}

// ---------------- 5) emit: segmented weighted sum, float4, 192 thr/block ----------------
__global__ void k_emit(const float* __restrict__ x, float* __restrict__ out) {
    int r = blockIdx.x, b = blockIdx.y;
    int tid = threadIdx.x;                                // 192 threads, one float4 each
    float4* orow = (float4*)(out + ((size_t)b*SS + r) * DD);
    int nf = d_nf[b];
    if (r >= nf) {
        orow[tid] = make_float4(0.f, 0.f, 0.f, 0.f);
        return;
    }
    int base = b*SS;
    int t1 = d_tend[base + r];
    int t0 = (r == 0) ? -1 : d_tend[base + r - 1];
    const float4* xb = (const float4*)(x + (size_t)b*SS*DD);   // row stride DD/4 = 192
    float4 acc = make_float4(0.f, 0.f, 0.f, 0.f);
    if (r > 0) {
        float w = d_wbeg[base + r];
        float4 v = xb[(size_t)t0 * (DD/4) + tid];
        acc.x = w*v.x; acc.y = w*v.y; acc.z = w*v.z; acc.w = w*v.w;
    }
    for (int t = t0 + 1; t < t1; ++t) {
        float w = d_alpha[base + t];
        float4 v = xb[(size_t)t * (DD/4) + tid];
        acc.x = fmaf(w, v.x, acc.x); acc.y = fmaf(w, v.y, acc.y);
        acc.z = fmaf(w, v.z, acc.z); acc.w = fmaf(w, v.w, acc.w);
    }
    {
        float w = d_wend[base + r];
        float4 v = xb[(size_t)t1 * (DD/4) + tid];
        acc.x = fmaf(w, v.x, acc.x); acc.y = fmaf(w, v.y, acc.y);
        acc.z = fmaf(w, v.z, acc.z); acc.w = fmaf(w, v.w, acc.w);
    }
    orow[tid] = acc;
}

extern "C" void kernel_launch(void* const* d_in, const int* in_sizes, int n_in,
                              void* d_out, int out_size) {
    const float* x      = (const float*)d_in[0];   // (B,S,D) f32
    const int*   lens   = (const int*)  d_in[1];   // (B,) i32
    const float* conv_w = (const float*)d_in[2];   // (D,D,3)
    const float* conv_b = (const float*)d_in[3];   // (D,)
    const float* lin_w  = (const float*)d_in[4];   // (1,D)
    const float* lin_b  = (const float*)d_in[5];   // (1,)
    float* out = (float*)d_out;

    const int BSD = BB * SS * DD;
    int write_len = (out_size >= BSD + BB) ? 1 : 0;

    k_weff <<<dim3(9, OCHUNKS), 256>>>(conv_w, lin_w);
    k_weff2<<<10, 256>>>(conv_b, lin_w, lin_b);
    k_g    <<<BS / 8, 256>>>(x);
    k_alpha<<<BS / 256, 256>>>();
    k_scan <<<BB, 256>>>(lens, out + BSD, write_len);
    k_emit <<<dim3(SS, BB), 192>>>(x, out);
}